// round 16
// baseline (speedup 1.0000x reference)
#include <cuda_runtime.h>
#include <cuda_fp16.h>
#include <math.h>
#include <stdint.h>

// ---------------- problem constants ----------------
static constexpr int B_   = 4;
static constexpr int NTOK = 1569;
static constexpr int C_   = 768;
static constexpr int H_   = 12;
static constexpr int D_   = 64;
static constexpr int F_   = 9;            // CLS + 8 temporal tokens
static constexpr int BN   = B_ * NTOK;    // 6276
static constexpr int C3   = 3 * C_;       // 2304
static constexpr int DFF  = 4 * C_;       // 3072
static constexpr int SPLIT = 12;          // temporal-attention key split
static constexpr int NSP  = NTOK - F_;    // 1560 spatial keys
static constexpr int KPB  = NSP / SPLIT;  // 130 keys per block
static constexpr int SROWS = 32;          // spatial rows per block
static constexpr int SCH  = (NSP + SROWS - 1) / SROWS;  // 49

// ---------------- scratch (device globals; no allocs) ----------------
__device__ __align__(16) float g_qkv[BN * C3];        // qkv projection (fp32)
__device__ __align__(16) float g_out[BN * C_];        // proj output ("new x", fp32)
__device__ __align__(16) __half g_h[BN * C_];         // LN out (fp16)
__device__ __align__(16) __half g_at[BN * C_];        // attn out (fp16)
__device__ __align__(16) __half g_m[BN * DFF];        // fc1 out (fp16)
__device__ __align__(16) __half g_wq[C3 * C_];
__device__ __align__(16) __half g_wp[C_ * C_];
__device__ __align__(16) __half g_w1[DFF * C_];
__device__ __align__(16) __half g_w2[C_ * DFF];
__device__ float g_part[B_ * H_ * F_ * SPLIT * 66];   // split-softmax partials

// ---------------- helpers ----------------
__device__ __forceinline__ uint32_t smem_u32(const void* p) {
    uint32_t a;
    asm("{ .reg .u64 t; cvta.to.shared.u64 t, %1; cvt.u32.u64 %0, t; }" : "=r"(a) : "l"(p));
    return a;
}
__device__ __forceinline__ void cp16(uint32_t dst, const void* src, int sz) {
    asm volatile("cp.async.cg.shared.global [%0], [%1], 16, %2;" :: "r"(dst), "l"(src), "r"(sz) : "memory");
}
__device__ __forceinline__ void cp_commit() { asm volatile("cp.async.commit_group;" ::: "memory"); }
template <int N>
__device__ __forceinline__ void cp_wait() { asm volatile("cp.async.wait_group %0;" :: "n"(N) : "memory"); }

__device__ __forceinline__ void ldm_x4(uint32_t* r, uint32_t addr) {
    asm volatile("ldmatrix.sync.aligned.m8n8.x4.shared.b16 {%0,%1,%2,%3}, [%4];"
                 : "=r"(r[0]), "=r"(r[1]), "=r"(r[2]), "=r"(r[3]) : "r"(addr));
}
__device__ __forceinline__ void mma_f16(float* d, const uint32_t* a, uint32_t b0, uint32_t b1) {
    asm volatile("mma.sync.aligned.m16n8k16.row.col.f32.f16.f16.f32 "
                 "{%0,%1,%2,%3}, {%4,%5,%6,%7}, {%8,%9}, {%0,%1,%2,%3};"
                 : "+f"(d[0]), "+f"(d[1]), "+f"(d[2]), "+f"(d[3])
                 : "r"(a[0]), "r"(a[1]), "r"(a[2]), "r"(a[3]), "r"(b0), "r"(b1));
}

// ---------------- segmented, vectorized weight convert (fp32 -> fp16) ----------------
static constexpr int WSEG0 = C3 * C_;
static constexpr int WSEG1 = WSEG0 + C_ * C_;
static constexpr int WSEG2 = WSEG1 + DFF * C_;
static constexpr int WTOT  = WSEG2 + C_ * DFF;

__global__ void __launch_bounds__(256) cvt_seg(const float* __restrict__ wq,
                                               const float* __restrict__ wp,
                                               const float* __restrict__ w1,
                                               const float* __restrict__ w2,
                                               int lo, int hi) {
    int i4 = lo + (blockIdx.x * 256 + threadIdx.x) * 4;
    if (i4 >= hi) return;
    const float* src; __half* dst; int loc;
    if (i4 < WSEG0)      { src = wq; dst = g_wq; loc = i4; }
    else if (i4 < WSEG1) { src = wp; dst = g_wp; loc = i4 - WSEG0; }
    else if (i4 < WSEG2) { src = w1; dst = g_w1; loc = i4 - WSEG1; }
    else                 { src = w2; dst = g_w2; loc = i4 - WSEG2; }
    float4 v = *(const float4*)(src + loc);
    __half2* hp = (__half2*)(dst + loc);
    hp[0] = __halves2half2(__float2half_rn(v.x), __float2half_rn(v.y));
    hp[1] = __halves2half2(__float2half_rn(v.z), __float2half_rn(v.w));
}

// ---------------- output-init kernels (absorb bias / residual for split-K) ----------------
__global__ void __launch_bounds__(256) init_out1(const float* __restrict__ bias) {
    int idx = (blockIdx.x * 256 + threadIdx.x) * 4;
    if (idx < BN * C_) *(float4*)&g_out[idx] = *(const float4*)&bias[idx % C_];
}
__global__ void __launch_bounds__(256) init_out3(const float* __restrict__ bias,
                                                 float* __restrict__ out) {
    int idx = (blockIdx.x * 256 + threadIdx.x) * 4;
    if (idx < BN * C_) {
        float4 g = *(const float4*)&g_out[idx];
        float4 b = *(const float4*)&bias[idx % C_];
        *(float4*)&out[idx] = make_float4(g.x + b.x, g.y + b.y, g.z + b.z, g.w + b.w);
    }
}

// ---------------- LayerNorm -> fp16 into g_h ----------------
template <bool FROM_OUT>
__global__ void __launch_bounds__(256) ln_kernel(const float* __restrict__ ext_in,
                                                 const float* __restrict__ gam,
                                                 const float* __restrict__ bet) {
    const float* in = FROM_OUT ? g_out : ext_in;
    int row = blockIdx.x;
    const float* x = in + (size_t)row * C_;
    int tid = threadIdx.x;
    float v0 = x[tid], v1 = x[tid + 256], v2 = x[tid + 512];
    float s  = v0 + v1 + v2;
    float ss = v0 * v0 + v1 * v1 + v2 * v2;
#pragma unroll
    for (int off = 16; off; off >>= 1) {
        s  += __shfl_xor_sync(0xffffffffu, s, off);
        ss += __shfl_xor_sync(0xffffffffu, ss, off);
    }
    __shared__ float sm[8], sm2[8], stats[2];
    int warp = tid >> 5, lane = tid & 31;
    if (lane == 0) { sm[warp] = s; sm2[warp] = ss; }
    __syncthreads();
    if (tid == 0) {
        float S = 0.f, SS = 0.f;
#pragma unroll
        for (int w = 0; w < 8; w++) { S += sm[w]; SS += sm2[w]; }
        float mean = S * (1.0f / C_);
        float var  = SS * (1.0f / C_) - mean * mean;
        stats[0] = mean;
        stats[1] = rsqrtf(var + 1e-5f);
    }
    __syncthreads();
    float mean = stats[0], rstd = stats[1];
    size_t base = (size_t)row * C_;
#pragma unroll
    for (int t = 0; t < 3; t++) {
        int c = tid + t * 256;
        float v = t == 0 ? v0 : (t == 1 ? v1 : v2);
        float y = (v - mean) * rstd * gam[c] + bet[c];
        g_h[base + c] = __float2half_rn(y);
    }
}

// ---------------- HMMA GEMM: C[M,Nn] = A[M,K] @ W[Nn,K]^T (plain fp16 x fp16) ----------------
static constexpr int STAGE_BYTES = 32768;   // A 16KB | W 16KB, xor-swizzled
static constexpr int SMEM_DYN = 2 * STAGE_BYTES;   // 64 KB

template <int CFG>
__global__ void __launch_bounds__(256, 2)
gemm_mma(const float* __restrict__ bias, float* __restrict__ ext_out) {
    constexpr int Nn = (CFG == 0) ? C3 : (CFG == 2) ? DFF : C_;
    constexpr int K  = (CFG == 3) ? DFF : C_;
    constexpr bool SK = (CFG == 1 || CFG == 3);
    constexpr int NCH = (K / 64) / (SK ? 2 : 1);

    const __half* A = (CFG == 0 || CFG == 2) ? g_h : (CFG == 1) ? g_at : g_m;
    const __half* W = (CFG == 0) ? g_wq : (CFG == 1) ? g_wp : (CFG == 2) ? g_w1 : g_w2;

    extern __shared__ char smraw[];
    uint32_t sbu = smem_u32(smraw);

    int tid = threadIdx.x, lane = tid & 31, wid = tid >> 5;
    int n0 = blockIdx.x * 128, m0 = blockIdx.y * 128;
    int c0 = SK ? (int)blockIdx.z * NCH : 0;
    int wm0 = (wid & 3) * 32, wn0 = (wid >> 2) * 64;

    auto issue = [&](int c, int s) {
        int k0 = c * 64;
        uint32_t sb = sbu + (uint32_t)s * STAGE_BYTES;
#pragma unroll
        for (int it = 0; it < 4; it++) {
            int idx = tid + it * 256;          // 0..1023
            int row = idx >> 3, unit = idx & 7;
            uint32_t soff = (uint32_t)row * 128u + (uint32_t)((unit ^ (row & 7)) << 4);
            int grA = m0 + row;
            int szA = (grA < BN) ? 16 : 0;
            cp16(sb + soff, A + (size_t)grA * K + k0 + unit * 8, szA);
            cp16(sb + 16384 + soff, W + (size_t)(n0 + row) * K + k0 + unit * 8, 16);
        }
        cp_commit();
    };

    float d[2][8][4];
#pragma unroll
    for (int i = 0; i < 2; i++)
#pragma unroll
        for (int j = 0; j < 8; j++)
#pragma unroll
            for (int q = 0; q < 4; q++) d[i][j][q] = 0.f;

    issue(c0, 0);
    for (int cc = 0; cc < NCH; cc++) {
        if (cc + 1 < NCH) { issue(c0 + cc + 1, (cc + 1) & 1); cp_wait<1>(); }
        else              { cp_wait<0>(); }
        __syncthreads();
        uint32_t sb = sbu + (uint32_t)(cc & 1) * STAGE_BYTES;
#pragma unroll
        for (int kk = 0; kk < 4; kk++) {
            uint32_t a[2][4];
#pragma unroll
            for (int mt = 0; mt < 2; mt++) {
                int row = wm0 + mt * 16 + (lane & 15);
                int unit = kk * 2 + (lane >> 4);
                uint32_t off = (uint32_t)row * 128u + (uint32_t)((unit ^ (row & 7)) << 4);
                ldm_x4(a[mt], sb + off);
            }
#pragma unroll
            for (int ng = 0; ng < 4; ng++) {
                int row = wn0 + ng * 16 + (lane & 15);
                int unit = kk * 2 + (lane >> 4);
                uint32_t off = (uint32_t)row * 128u + (uint32_t)((unit ^ (row & 7)) << 4);
                uint32_t b4[4];
                ldm_x4(b4, sb + 16384 + off);
#pragma unroll
                for (int mt = 0; mt < 2; mt++)
#pragma unroll
                    for (int hf = 0; hf < 2; hf++) {
                        mma_f16(d[mt][ng * 2 + hf], a[mt], b4[hf], b4[hf + 2]);
                    }
            }
        }
        __syncthreads();
    }

    // epilogue
#pragma unroll
    for (int mt = 0; mt < 2; mt++) {
#pragma unroll
        for (int half = 0; half < 2; half++) {
            int grow = m0 + wm0 + mt * 16 + (lane >> 2) + half * 8;
            if (grow >= BN) continue;
#pragma unroll
            for (int nt = 0; nt < 8; nt++) {
                int gc = n0 + wn0 + nt * 8 + (lane & 3) * 2;
                float v0 = d[mt][nt][half * 2 + 0];
                float v1 = d[mt][nt][half * 2 + 1];
                size_t o = (size_t)grow * Nn + gc;
                if constexpr (CFG == 0) {
                    *(float2*)&g_qkv[o] = make_float2(v0, v1);
                } else if constexpr (CFG == 1) {
                    atomicAdd(&g_out[o], v0);
                    atomicAdd(&g_out[o + 1], v1);
                } else if constexpr (CFG == 2) {
                    v0 += bias[gc]; v1 += bias[gc + 1];
                    v0 = 0.5f * v0 * (1.0f + erff(v0 * 0.70710678f));
                    v1 = 0.5f * v1 * (1.0f + erff(v1 * 0.70710678f));
                    g_m[o]     = __float2half_rn(v0);
                    g_m[o + 1] = __float2half_rn(v1);
                } else {
                    atomicAdd(&ext_out[o], v0);
                    atomicAdd(&ext_out[o + 1], v1);
                }
            }
        }
    }
}

// ---------------- attention, spatial rows: 8-lanes-per-row (4 rows/warp) ----------------
__global__ void __launch_bounds__(256) attn_spatial() {
    const float* qkv = g_qkv;
    int bid   = blockIdx.x;
    int chunk = bid % SCH;
    int bh    = bid / SCH;
    int h     = bh % H_;
    int b     = bh / H_;

    __shared__ float ks[F_][D_], vs[F_][D_];
    int tid = threadIdx.x;
    for (int idx = tid; idx < F_ * D_; idx += 256) {
        int j = idx / D_, dd = idx % D_;
        const float* base = qkv + ((size_t)(b * NTOK + j)) * C3 + h * D_;
        ks[j][dd] = base[C_ + dd];
        vs[j][dd] = base[2 * C_ + dd];
    }
    __syncthreads();

    int warp = tid >> 5, lane = tid & 31;
    int sub = lane >> 3, d0 = lane & 7;
    int roff = chunk * SROWS + warp * 4 + sub;      // 0..1567
    bool ok = roff < NSP;
    int i = F_ + (ok ? roff : NSP - 1);             // clamp loads, guard stores
    const float* q = qkv + ((size_t)(b * NTOK + i)) * C3 + h * D_;

    float qreg[8];
#pragma unroll
    for (int k = 0; k < 8; k++) qreg[k] = q[d0 + 8 * k];

    float lg[F_];
#pragma unroll
    for (int j = 0; j < F_; j++) {
        float p = 0.f;
#pragma unroll
        for (int k = 0; k < 8; k++) p += qreg[k] * ks[j][d0 + 8 * k];
        p += __shfl_xor_sync(0xffffffffu, p, 1);
        p += __shfl_xor_sync(0xffffffffu, p, 2);
        p += __shfl_xor_sync(0xffffffffu, p, 4);
        lg[j] = p * 0.125f;
    }
    float m = lg[0];
#pragma unroll
    for (int j = 1; j < F_; j++) m = fmaxf(m, lg[j]);
    float wj[F_], s = 0.f;
#pragma unroll
    for (int j = 0; j < F_; j++) { wj[j] = expf(lg[j] - m); s += wj[j]; }
    float inv = 1.0f / s;

    float acc[8];
#pragma unroll
    for (int k = 0; k < 8; k++) acc[k] = 0.f;
#pragma unroll
    for (int j = 0; j < F_; j++)
#pragma unroll
        for (int k = 0; k < 8; k++) acc[k] += wj[j] * vs[j][d0 + 8 * k];

    if (ok) {
        size_t off0 = ((size_t)(b * NTOK + i)) * C_ + h * D_;
#pragma unroll
        for (int k = 0; k < 8; k++)
            g_at[off0 + d0 + 8 * k] = __float2half_rn(acc[k] * inv);
    }
}

// ---------------- temporal rows: smem-tiled, 9 warps, paired pass-1, K-tile reused for V ----------------
__global__ void __launch_bounds__(288) attn_tpart() {
    const float* qkv = g_qkv;
    int bid = blockIdx.x;
    int sp = bid % SPLIT;
    int bh = bid / SPLIT;
    int h  = bh % H_;
    int b  = bh / H_;

    __shared__ float qsh[F_][D_];            // 2.3 KB
    __shared__ float kt[KPB + 1][D_ + 3];    // 131 x 67 fp32 = 35.1 KB (K, then reused for V)
    __shared__ float lgs[KPB + 1][F_];       // 4.7 KB
    __shared__ float red[F_][2];             // Mb, Sb

    int tid = threadIdx.x, w = tid >> 5, lane = tid & 31;
    int base = F_ + sp * KPB;
    int cnt = KPB + (sp == 0 ? 1 : 0);

    // stage Q and K tile
    for (int idx = tid; idx < F_ * D_; idx += 288)
        qsh[idx / D_][idx % D_] = qkv[((size_t)(b * NTOK + idx / D_)) * C3 + h * D_ + idx % D_];
    for (int idx = tid; idx < KPB * D_; idx += 288) {
        int j = idx / D_, d = idx % D_;
        kt[j][d] = qkv[((size_t)(b * NTOK + base + j)) * C3 + C_ + h * D_ + d];
    }
    if (sp == 0)
        for (int d = tid; d < D_; d += 288)
            kt[KPB][d] = qkv[((size_t)(b * NTOK + 0)) * C3 + C_ + h * D_ + d];
    __syncthreads();

    // pass 1: pair of threads per key (even/odd 32-wide D halves), one shfl to combine
    {
        int key = tid >> 1;
        int keyc = key < cnt ? key : cnt - 1;   // clamp for safe loads
        int half = tid & 1;
        int dbase = half * 32;
        float acc[F_];
#pragma unroll
        for (int i = 0; i < F_; i++) acc[i] = 0.f;
        for (int d = dbase; d < dbase + 32; d++) {
            float kd = kt[keyc][d];
#pragma unroll
            for (int i = 0; i < F_; i++) acc[i] += qsh[i][d] * kd;
        }
        bool cls = (keyc == KPB);
#pragma unroll
        for (int i = 0; i < F_; i++) {
            float p = acc[i] + __shfl_xor_sync(0xffffffffu, acc[i], 1);
            if (key < cnt && half == 0)
                lgs[key][i] = (cls && i > 0) ? -1e30f : p * 0.125f;
        }
    }
    __syncthreads();   // pass 1 done: kt (K) dead, lgs live

    // stage V into kt (reuse)
    for (int idx = tid; idx < KPB * D_; idx += 288) {
        int j = idx / D_, d = idx % D_;
        kt[j][d] = qkv[((size_t)(b * NTOK + base + j)) * C3 + 2 * C_ + h * D_ + d];
    }
    if (sp == 0)
        for (int d = tid; d < D_; d += 288)
            kt[KPB][d] = qkv[((size_t)(b * NTOK + 0)) * C3 + 2 * C_ + h * D_ + d];

    // per-row block max / expsum (warp r = row r; 9 warps)
    if (w < F_) {
        int r = w;
        float mx = -1e30f, sm = 0.f;
        for (int t = lane; t < cnt; t += 32) {
            float lg = lgs[t][r];
            if (lg > mx) { sm *= expf(mx - lg); mx = lg; }
            sm += expf(lg - mx);
        }
#pragma unroll
        for (int off = 16; off; off >>= 1) {
            float mo = __shfl_xor_sync(0xffffffffu, mx, off);
            float so = __shfl_xor_sync(0xffffffffu, sm, off);
            float Mx = fmaxf(mx, mo);
            sm = sm * expf(mx - Mx) + so * expf(mo - Mx);
            mx = Mx;
        }
        if (lane == 0) { red[r][0] = mx; red[r][1] = sm; }
    }
    __syncthreads();   // V staged + reductions done

    // pass 2: warp r owns row r; V from smem (conflict-free)
    if (w < F_) {
        int r = w;
        float M = red[r][0];
        float a0 = 0.f, a1 = 0.f;
        for (int t = 0; t < cnt; t++) {
            float w8 = expf(lgs[t][r] - M);
            a0 += w8 * kt[t][lane];
            a1 += w8 * kt[t][lane + 32];
        }
        float* pp = g_part + (size_t)(((bh * F_ + r) * SPLIT) + sp) * 66;
        pp[2 + lane]      = a0;
        pp[2 + lane + 32] = a1;
        if (lane == 0) { pp[0] = M; pp[1] = red[r][1]; }
    }
}

__global__ void __launch_bounds__(64) attn_tred() {
    int t = blockIdx.x;                 // t = bh*F + i
    int i  = t % F_;
    int bh = t / F_;
    int h = bh % H_;
    int b = bh / H_;
    int d = threadIdx.x;

    float M = -1e30f;
    float ms[SPLIT], ss[SPLIT];
#pragma unroll
    for (int sp = 0; sp < SPLIT; sp++) {
        const float* pp = g_part + (size_t)(t * SPLIT + sp) * 66;
        ms[sp] = pp[0]; ss[sp] = pp[1];
        M = fmaxf(M, ms[sp]);
    }
    float S = 0.f, acc = 0.f;
#pragma unroll
    for (int sp = 0; sp < SPLIT; sp++) {
        float e = expf(ms[sp] - M);
        S += ss[sp] * e;
        acc += g_part[(size_t)(t * SPLIT + sp) * 66 + 2 + d] * e;
    }
    g_at[((size_t)(b * NTOK + i)) * C_ + h * D_ + d] = __float2half_rn(acc / S);
}

// ---------------- launch (stream fork/join, capture-safe) ----------------
extern "C" void kernel_launch(void* const* d_in, const int* in_sizes, int n_in,
                              void* d_out, int out_size) {
    const float* x     = (const float*)d_in[0];
    const float* ln_g  = (const float*)d_in[1];
    const float* ln_b  = (const float*)d_in[2];
    const float* qkvw  = (const float*)d_in[3];
    const float* projw = (const float*)d_in[4];
    const float* projb = (const float*)d_in[5];
    const float* fc1w  = (const float*)d_in[6];
    const float* fc1b  = (const float*)d_in[7];
    const float* fc2w  = (const float*)d_in[8];
    const float* fc2b  = (const float*)d_in[9];
    float* out = (float*)d_out;

    cudaFuncSetAttribute(gemm_mma<0>, cudaFuncAttributeMaxDynamicSharedMemorySize, SMEM_DYN);
    cudaFuncSetAttribute(gemm_mma<1>, cudaFuncAttributeMaxDynamicSharedMemorySize, SMEM_DYN);
    cudaFuncSetAttribute(gemm_mma<2>, cudaFuncAttributeMaxDynamicSharedMemorySize, SMEM_DYN);
    cudaFuncSetAttribute(gemm_mma<3>, cudaFuncAttributeMaxDynamicSharedMemorySize, SMEM_DYN);

    cudaStream_t s2;
    cudaStreamCreateWithFlags(&s2, cudaStreamNonBlocking);
    cudaEvent_t e0, e1, e2, e3, e4, e5;
    cudaEventCreateWithFlags(&e0, cudaEventDisableTiming);
    cudaEventCreateWithFlags(&e1, cudaEventDisableTiming);
    cudaEventCreateWithFlags(&e2, cudaEventDisableTiming);
    cudaEventCreateWithFlags(&e3, cudaEventDisableTiming);
    cudaEventCreateWithFlags(&e4, cudaEventDisableTiming);
    cudaEventCreateWithFlags(&e5, cudaEventDisableTiming);

    const int INIT_BLOCKS = (BN * C_ / 4 + 255) / 256;
    cudaStream_t m = 0;

    // ---- fork 1: s2: ln1 -> (during gemm0) cvt_rest + init_out1 ; main: cvt_wq ----
    cudaEventRecord(e0, m);
    cudaStreamWaitEvent(s2, e0, 0);
    ln_kernel<false><<<BN, 256, 0, s2>>>(x, ln_g, ln_b);
    cudaEventRecord(e1, s2);                 // ln1 done
    cvt_seg<<<(WSEG0 / 4 + 255) / 256, 256, 0, m>>>(qkvw, projw, fc1w, fc2w, 0, WSEG0);
    cudaStreamWaitEvent(m, e1, 0);

    // 2. g_qkv = g_h @ qkv_w^T (main); shadow work on s2
    gemm_mma<0><<<dim3(C3 / 128, (BN + 127) / 128), 256, SMEM_DYN, m>>>(nullptr, nullptr);
    cudaEventRecord(e2, m);                  // qkv ready
    cvt_seg<<<((WTOT - WSEG0) / 4 + 255) / 256, 256, 0, s2>>>(qkvw, projw, fc1w, fc2w, WSEG0, WTOT);
    init_out1<<<INIT_BLOCKS, 256, 0, s2>>>(projb);

    // ---- fork 2: s2: tpart->tred ; main: spatial ----
    cudaStreamWaitEvent(s2, e2, 0);
    attn_tpart<<<B_ * H_ * SPLIT, 288, 0, s2>>>();
    attn_tred<<<B_ * H_ * F_, 64, 0, s2>>>();
    attn_spatial<<<B_ * H_ * SCH, 256, 0, m>>>();
    cudaEventRecord(e3, s2);
    cudaStreamWaitEvent(m, e3, 0);

    // 4. g_out += g_at @ proj_w^T  (split-K=2, atomic)
    gemm_mma<1><<<dim3(C_ / 128, (BN + 127) / 128, 2), 256, SMEM_DYN, m>>>(nullptr, nullptr);

    // ---- fork 3: s2: init_out3 ; main: ln2 + fc1 ----
    cudaEventRecord(e4, m);
    cudaStreamWaitEvent(s2, e4, 0);
    init_out3<<<INIT_BLOCKS, 256, 0, s2>>>(fc2b, out);
    ln_kernel<true><<<BN, 256, 0, m>>>(nullptr, ln_g, ln_b);
    gemm_mma<2><<<dim3(DFF / 128, (BN + 127) / 128), 256, SMEM_DYN, m>>>(fc1b, nullptr);
    cudaEventRecord(e5, s2);
    cudaStreamWaitEvent(m, e5, 0);

    // 7. out += g_m @ fc2_w^T  (split-K=2, atomic)
    gemm_mma<3><<<dim3(C_ / 128, (BN + 127) / 128, 2), 256, SMEM_DYN, m>>>(nullptr, out);
}